// round 3
// baseline (speedup 1.0000x reference)
#include <cuda_runtime.h>
#include <math.h>

#define Bz 64
#define Tz 512
#define INz 1024
#define Hz 1024
#define Cz 512

#define RBLOCKS 128
#define RTHREADS 128

// ---------------- persistent scratch (static __device__ = allowed) ----------
__device__ float d_xc[(size_t)Bz * Tz * Cz];        // xc, then c (in-place)   64 MB
__device__ float d_g[(size_t)Bz * Tz * Hz];         // g = c @ Uc^T           128 MB
__device__ float d_part[(size_t)RBLOCKS * 64 * 128];// per-step partials        4 MB
__device__ float d_hTr[Hz * Bz];                    // h transposed [n][m]
__device__ unsigned d_gcount;                       // grid barrier counter

// ---------------- init: transpose h0, reset barrier -------------------------
__global__ void init_kernel(const float* __restrict__ h0) {
    int idx = blockIdx.x * blockDim.x + threadIdx.x;
    if (idx == 0) d_gcount = 0u;
    if (idx < Hz * Bz) {
        int n = idx >> 6, m = idx & 63;
        d_hTr[idx] = h0[m * Hz + n];
    }
}

// ---------------- EMA scan over T (in-place xc -> c), emit c_T --------------
__global__ void scan_kernel(const float* __restrict__ c0, float* __restrict__ outCT) {
    int idx = blockIdx.x * blockDim.x + threadIdx.x;   // 0 .. B*C-1
    int b = idx >> 9;            // /512
    int ch = idx & 511;
    float c = c0[idx];
    float* p = d_xc + (size_t)b * Tz * Cz + ch;
    const float a = 0.95f, na = 0.05f;
#pragma unroll 4
    for (int t = 0; t < Tz; ++t) {
        float v = p[t * Cz];
        c = na * c + a * v;
        p[t * Cz] = c;
    }
    outCT[idx] = c;
}

// ---------------- fp32 SGEMM:  C[M,N] = A[M,K] @ Bw[N,K]^T (+ bias) ---------
// block tile 128x128, 256 threads, 8x8 per-thread tile, K-chunk 16
__global__ __launch_bounds__(256) void sgemm_tn(
    const float* __restrict__ A, const float* __restrict__ Bw,
    const float* __restrict__ bias, float* __restrict__ Cout,
    int N, int K)
{
    __shared__ float As[16][132];
    __shared__ float Bs[16][132];
    const int tid = threadIdx.x;
    const int tx = tid & 15, ty = tid >> 4;
    const int m0 = blockIdx.x * 128, n0 = blockIdx.y * 128;
    const int lrow = tid >> 2;          // 0..63
    const int lkq  = (tid & 3) << 2;    // 0,4,8,12

    float acc[8][8];
#pragma unroll
    for (int i = 0; i < 8; ++i)
#pragma unroll
        for (int j = 0; j < 8; ++j) acc[i][j] = 0.f;

    for (int kc = 0; kc < K; kc += 16) {
#pragma unroll
        for (int h = 0; h < 2; ++h) {
            int row = lrow + h * 64;
            float4 va = *reinterpret_cast<const float4*>(&A[(size_t)(m0 + row) * K + kc + lkq]);
            As[lkq + 0][row] = va.x; As[lkq + 1][row] = va.y;
            As[lkq + 2][row] = va.z; As[lkq + 3][row] = va.w;
            float4 vb = *reinterpret_cast<const float4*>(&Bw[(size_t)(n0 + row) * K + kc + lkq]);
            Bs[lkq + 0][row] = vb.x; Bs[lkq + 1][row] = vb.y;
            Bs[lkq + 2][row] = vb.z; Bs[lkq + 3][row] = vb.w;
        }
        __syncthreads();
#pragma unroll
        for (int k = 0; k < 16; ++k) {
            float4 a0 = *reinterpret_cast<const float4*>(&As[k][ty * 4]);
            float4 a1 = *reinterpret_cast<const float4*>(&As[k][ty * 4 + 64]);
            float4 b0 = *reinterpret_cast<const float4*>(&Bs[k][tx * 4]);
            float4 b1 = *reinterpret_cast<const float4*>(&Bs[k][tx * 4 + 64]);
            float am[8] = {a0.x, a0.y, a0.z, a0.w, a1.x, a1.y, a1.z, a1.w};
            float bn[8] = {b0.x, b0.y, b0.z, b0.w, b1.x, b1.y, b1.z, b1.w};
#pragma unroll
            for (int i = 0; i < 8; ++i)
#pragma unroll
                for (int j = 0; j < 8; ++j)
                    acc[i][j] = fmaf(am[i], bn[j], acc[i][j]);
        }
        __syncthreads();
    }

    float bv[8] = {0.f, 0.f, 0.f, 0.f, 0.f, 0.f, 0.f, 0.f};
    if (bias) {
#pragma unroll
        for (int j = 0; j < 4; ++j) {
            bv[j]     = bias[n0 + tx * 4 + j];
            bv[4 + j] = bias[n0 + 64 + tx * 4 + j];
        }
    }
#pragma unroll
    for (int hm = 0; hm < 2; ++hm) {
#pragma unroll
        for (int i = 0; i < 4; ++i) {
            int ii = hm * 4 + i;
            int row = m0 + hm * 64 + ty * 4 + i;
            float4 o0 = make_float4(acc[ii][0] + bv[0], acc[ii][1] + bv[1],
                                    acc[ii][2] + bv[2], acc[ii][3] + bv[3]);
            float4 o1 = make_float4(acc[ii][4] + bv[4], acc[ii][5] + bv[5],
                                    acc[ii][6] + bv[6], acc[ii][7] + bv[7]);
            *reinterpret_cast<float4*>(&Cout[(size_t)row * N + n0 + tx * 4]) = o0;
            *reinterpret_cast<float4*>(&Cout[(size_t)row * N + n0 + 64 + tx * 4]) = o1;
        }
    }
}

// ---------------- grid-wide barrier (all 128 blocks co-resident) ------------
__device__ __forceinline__ void gsync(unsigned& target) {
    __threadfence();
    __syncthreads();
    target += RBLOCKS;
    if (threadIdx.x == 0) {
        atomicAdd(&d_gcount, 1u);
        while (*(volatile unsigned*)&d_gcount < target) { __nanosleep(32); }
    }
    __syncthreads();
}

// ---------------- persistent recurrence kernel ------------------------------
// grid 128 = 8 N-tiles (128 cols) x 16 K-slices (64), 128 threads/block
__global__ __launch_bounds__(RTHREADS, 1) void recur_kernel(
    const float* __restrict__ Vh, float* __restrict__ out, float* __restrict__ outHT)
{
    __shared__ float vhs[64 * 128];   // Vh slice [k][n], resident all steps
    __shared__ float hs[64 * 64];     // h slice  [k][m], restaged per step

    const int tid = threadIdx.x;
    const int bid = blockIdx.x;
    const int nb = bid >> 4, kb = bid & 15;
    const int n0 = nb * 128, k0 = kb * 64;
    const int tx = tid & 15, ty = tid >> 4;   // ty 0..7, tx 0..15

    // stage Vh slice once: vhs[k][n] = Vh[n0+n][k0+k]
    for (int it = 0; it < 64; ++it) {
        int lin = it * 128 + tid;
        int n = lin >> 6, k = lin & 63;
        vhs[k * 128 + n] = Vh[(size_t)(n0 + n) * Hz + k0 + k];
    }

    // phase-2 element assignment: 4 consecutive n per thread, m-major
    const int e0 = bid * 512 + tid * 4;
    const int pm = e0 >> 10;
    const int pn = e0 & 1023;
    const int pnb = pn >> 7, pnl = pn & 127;

    float* partW = d_part + (size_t)bid * (64 * 128);
    unsigned target = 0;
    __syncthreads();

    for (int t = 0; t < Tz; ++t) {
        // ---- phase 1: stage h slice (transposed buffer -> coalesced float4) ----
        {
            const float4* src = reinterpret_cast<const float4*>(d_hTr + (size_t)k0 * 64);
            float4* dst = reinterpret_cast<float4*>(hs);
#pragma unroll
            for (int r = 0; r < 8; ++r) {
                int i = r * 128 + tid;            // 0..1023 float4 index
                dst[i] = __ldcg(&src[i]);
            }
        }
        __syncthreads();

        float acc[8][8];
#pragma unroll
        for (int i = 0; i < 8; ++i)
#pragma unroll
            for (int j = 0; j < 8; ++j) acc[i][j] = 0.f;

#pragma unroll 8
        for (int k = 0; k < 64; ++k) {
            float4 a0 = *reinterpret_cast<const float4*>(&hs[k * 64 + ty * 4]);
            float4 a1 = *reinterpret_cast<const float4*>(&hs[k * 64 + ty * 4 + 32]);
            float4 b0 = *reinterpret_cast<const float4*>(&vhs[k * 128 + tx * 4]);
            float4 b1 = *reinterpret_cast<const float4*>(&vhs[k * 128 + tx * 4 + 64]);
            float am[8] = {a0.x, a0.y, a0.z, a0.w, a1.x, a1.y, a1.z, a1.w};
            float bn[8] = {b0.x, b0.y, b0.z, b0.w, b1.x, b1.y, b1.z, b1.w};
#pragma unroll
            for (int i = 0; i < 8; ++i)
#pragma unroll
                for (int j = 0; j < 8; ++j)
                    acc[i][j] = fmaf(am[i], bn[j], acc[i][j]);
        }

        // write partials (L2-coherent)
#pragma unroll
        for (int ii = 0; ii < 8; ++ii) {
            int m = (ii < 4) ? (ty * 4 + ii) : (32 + ty * 4 + (ii - 4));
            float4 v0 = make_float4(acc[ii][0], acc[ii][1], acc[ii][2], acc[ii][3]);
            float4 v1 = make_float4(acc[ii][4], acc[ii][5], acc[ii][6], acc[ii][7]);
            __stcg(reinterpret_cast<float4*>(&partW[m * 128 + tx * 4]), v0);
            __stcg(reinterpret_cast<float4*>(&partW[m * 128 + 64 + tx * 4]), v1);
        }

        gsync(target);   // partials visible

        // ---- phase 2: reduce 16 partials + g_t, tanh, scatter h ----
        float4 s = *reinterpret_cast<const float4*>(&d_g[((size_t)pm * Tz + t) * Hz + pn]);
#pragma unroll
        for (int k2 = 0; k2 < 16; ++k2) {
            float4 p = __ldcg(reinterpret_cast<const float4*>(
                &d_part[(size_t)(pnb * 16 + k2) * (64 * 128) + pm * 128 + pnl]));
            s.x += p.x; s.y += p.y; s.z += p.z; s.w += p.w;
        }
        float4 hv = make_float4(tanhf(s.x), tanhf(s.y), tanhf(s.z), tanhf(s.w));

        *reinterpret_cast<float4*>(&out[((size_t)pm * Tz + t) * Hz + pn]) = hv;
        __stcg(&d_hTr[(pn + 0) * 64 + pm], hv.x);
        __stcg(&d_hTr[(pn + 1) * 64 + pm], hv.y);
        __stcg(&d_hTr[(pn + 2) * 64 + pm], hv.z);
        __stcg(&d_hTr[(pn + 3) * 64 + pm], hv.w);
        if (t == Tz - 1) {
            *reinterpret_cast<float4*>(&outHT[(size_t)pm * Hz + pn]) = hv;
        }

        gsync(target);   // h ready for next step
    }
}

// ---------------- launch ----------------------------------------------------
extern "C" void kernel_launch(void* const* d_in, const int* in_sizes, int n_in,
                              void* d_out, int out_size) {
    const float* x  = (const float*)d_in[0];
    const float* h0 = (const float*)d_in[1];
    const float* c0 = (const float*)d_in[2];
    const float* Wx = (const float*)d_in[3];
    const float* bx = (const float*)d_in[4];
    const float* Uc = (const float*)d_in[5];
    const float* Vh = (const float*)d_in[6];

    float* out   = (float*)d_out;                       // [B,T,H]
    float* outHT = out + (size_t)Bz * Tz * Hz;          // [B,H]
    float* outCT = outHT + (size_t)Bz * Hz;             // [B,C]

    float *dxc, *dg;
    cudaGetSymbolAddress((void**)&dxc, d_xc);
    cudaGetSymbolAddress((void**)&dg, d_g);

    // 1) init: transpose h0, reset barrier
    init_kernel<<<(Hz * Bz + 255) / 256, 256>>>(h0);

    // 2) xc = x @ Wx^T + bx   (M=32768, N=512, K=1024)
    sgemm_tn<<<dim3((Bz * Tz) / 128, Cz / 128), 256>>>(x, Wx, bx, dxc, Cz, INz);

    // 3) EMA scan: xc -> c (in place), write c_T
    scan_kernel<<<(Bz * Cz) / 256, 256>>>(c0, outCT);

    // 4) g = c @ Uc^T   (M=32768, N=1024, K=512)
    sgemm_tn<<<dim3((Bz * Tz) / 128, Hz / 128), 256>>>(dxc, Uc, nullptr, dg, Hz, Cz);

    // 5) recurrence: h_t = tanh(g_t + h_{t-1} @ Vh^T), all 512 steps in one launch
    recur_kernel<<<RBLOCKS, RTHREADS>>>(Vh, out, outHT);
}